// round 17
// baseline (speedup 1.0000x reference)
#include <cuda_runtime.h>
#include <cstdint>

// x:      (16, 16, 64, 512)  f32
// kernel: (32, 16, 4)        f32
// points: (16, 3, 64, 512)  f32
// out:    (16, 32, 62, 510)  f32
#define CH_STRIDE 32768
#define HP 62
#define WP 510
#define OUT_PLANE (62*510)
#define KSTR 72                 // K smem stride (words)
#define DSTR 132                // epilogue smem stride (words)
#define FULLM 0xffffffffu

typedef unsigned long long u64;
typedef unsigned int u32;

__device__ __forceinline__ u64 pk(float lo, float hi) {
    u64 r; asm("mov.b64 %0, {%1,%2};" : "=l"(r) : "f"(lo), "f"(hi)); return r;
}
__device__ __forceinline__ void upk(u64 v, float& lo, float& hi) {
    asm("mov.b64 {%0,%1}, %2;" : "=f"(lo), "=f"(hi) : "l"(v));
}
__device__ __forceinline__ u64 fma2(u64 a, u64 b, u64 c) {
    u64 d; asm("fma.rn.f32x2 %0, %1, %2, %3;" : "=l"(d) : "l"(a), "l"(b), "l"(c)); return d;
}
__device__ __forceinline__ u64 add2(u64 a, u64 b) {
    u64 d; asm("add.rn.f32x2 %0, %1, %2;" : "=l"(d) : "l"(a), "l"(b)); return d;
}
__device__ __forceinline__ u64 neg2(u64 a) { return a ^ 0x8000000080000000ULL; }

__device__ __forceinline__ u32 tf32r(float f) {
    u32 r; asm("cvt.rna.tf32.f32 %0, %1;" : "=r"(r) : "f"(f)); return r;
}

__device__ __forceinline__ void mma_tf32(float& d0, float& d1, float& d2, float& d3,
                                         u32 a0, u32 a1, u32 a2, u32 a3,
                                         u32 b0, u32 b1) {
    asm volatile("mma.sync.aligned.m16n8k8.row.col.f32.tf32.tf32.f32 "
                 "{%0,%1,%2,%3}, {%4,%5,%6,%7}, {%8,%9}, {%0,%1,%2,%3};"
                 : "+f"(d0), "+f"(d1), "+f"(d2), "+f"(d3)
                 : "r"(a0), "r"(a1), "r"(a2), "r"(a3), "r"(b0), "r"(b1));
}

__global__ void __launch_bounds__(128, 5)
flex_conv_mma10_kernel(const float* __restrict__ x,
                       const float* __restrict__ kern,
                       const float* __restrict__ pts,
                       float* __restrict__ out)
{
    // C tile: 128 rows x 64 words. 8 groups/row, group idx swizzled pr^(row&7);
    // inside a group, logical word v stored at physical v ^ (4*((row>>2)&1)).
    __shared__ u32 Cs[128 * 64];        // 32 KB (reused as Dsm in epilogue)
    __shared__ u32 Ksm[32 * KSTR];      // 9.2 KB, fragment-pair-ordered

    const int tid  = threadIdx.x;
    const int lane = tid & 31;

    // Stage K: idx = o*64 + c; pairs (cq, cq+4) adjacent for LDS.64
    #pragma unroll
    for (int t = 0; t < 16; ++t) {
        int idx = t * 128 + tid;
        int o = idx >> 6, c = idx & 63;
        int pos = 2 * (c & 3) + ((c >> 2) & 1);
        Ksm[o * KSTR + (c >> 3) * 8 + pos] = tf32r(kern[idx]);
    }

    const int w = blockIdx.x * 128 + tid;   // 0..511, always in-bounds for f0
    const int h = blockIdx.y;
    const int b = blockIdx.z;

    // boundary reload offsets (clamped only for masked edge lanes)
    const int o1 = ((w + 1 < 512) ? (w + 1) : 511) - w;
    const int o2 = ((w + 2 < 512) ? (w + 2) : 511) - w;

    const float* xb = x   + ((b * 16) * 64 + h) * 512 + w;
    const float* pb = pts + ((b * 3)  * 64 + h) * 512 + w;

    const int h2 = (tid >> 2) & 1;      // half-swap selector for C stores

    // ---------------- phase 1: box sums; f=1,2 taps via warp shuffle ----------------
    #pragma unroll 1
    for (int half = 0; half < 2; ++half) {
        u64 A2[4], Bn[3][4], ctrq[3];
        #pragma unroll
        for (int j = 0; j < 4; ++j) { A2[j] = 0ull; Bn[0][j] = 0ull; Bn[1][j] = 0ull; Bn[2][j] = 0ull; }

        #pragma unroll
        for (int r = 0; r < 3; ++r) {
            u64 q0[3], q1[3], q2[3];
            #pragma unroll
            for (int d = 0; d < 3; ++d) {
                const float* prow = pb + d * CH_STRIDE + r * 512;
                float p0 = prow[0];
                float p1 = __shfl_down_sync(FULLM, p0, 1);
                float p2 = __shfl_down_sync(FULLM, p0, 2);
                if (lane == 31) p1 = prow[o1];
                if (lane >= 30) p2 = prow[o2];
                q0[d] = pk(p0, p0); q1[d] = pk(p1, p1); q2[d] = pk(p2, p2);
                if (r == 1) ctrq[d] = q1[d];     // center = pts[h+1][w+1]
            }
            #pragma unroll
            for (int j = 0; j < 4; ++j) {
                const int ch = half * 8 + 2 * j;
                const float* xr0 = xb + ch * CH_STRIDE + r * 512;
                const float* xr1 = xr0 + CH_STRIDE;
                float a0 = xr0[0], c0 = xr1[0];
                float a1 = __shfl_down_sync(FULLM, a0, 1);
                float a2 = __shfl_down_sync(FULLM, a0, 2);
                float c1 = __shfl_down_sync(FULLM, c0, 1);
                float c2 = __shfl_down_sync(FULLM, c0, 2);
                if (lane == 31) { a1 = xr0[o1]; c1 = xr1[o1]; }
                if (lane >= 30) { a2 = xr0[o2]; c2 = xr1[o2]; }
                u64 f0 = pk(a0, c0), f1 = pk(a1, c1), f2 = pk(a2, c2);
                A2[j] = add2(A2[j], add2(add2(f0, f1), f2));
                Bn[0][j] = fma2(q2[0], f2, fma2(q1[0], f1, fma2(q0[0], f0, Bn[0][j])));
                Bn[1][j] = fma2(q2[1], f2, fma2(q1[1], f1, fma2(q0[1], f0, Bn[1][j])));
                Bn[2][j] = fma2(q2[2], f2, fma2(q1[2], f1, fma2(q0[2], f0, Bn[2][j])));
            }
        }

        #pragma unroll
        for (int j = 0; j < 4; ++j) {
            const int pr = half * 4 + j;
            u64 C0 = fma2(ctrq[0], A2[j], neg2(Bn[0][j]));
            u64 C1 = fma2(ctrq[1], A2[j], neg2(Bn[1][j]));
            u64 C2 = fma2(ctrq[2], A2[j], neg2(Bn[2][j]));
            float c0l, c0h, c1l, c1h, c2l, c2h, al, ah;
            upk(C0, c0l, c0h); upk(C1, c1l, c1h); upk(C2, c2l, c2h); upk(A2[j], al, ah);

            u32* p = Cs + tid * 64 + ((pr ^ (tid & 7)) << 3);
            uint4 blkA = make_uint4(tf32r(c0l), tf32r(c0h), tf32r(c1l), tf32r(c1h));
            uint4 blkB = make_uint4(tf32r(c2l), tf32r(c2h), tf32r(al), tf32r(ah));
            *reinterpret_cast<uint4*>(p + 4 * h2)       = blkA;
            *reinterpret_cast<uint4*>(p + (4 * h2 ^ 4)) = blkB;
        }
    }
    __syncthreads();

    // ---------------- phase 2: out[128px, 32o] = C[128x64] * K^T ----------------
    const int wq    = tid >> 5;
    const int g     = lane >> 2;
    const int cq    = lane & 3;
    const int g2    = (g >> 2) & 1;
    const int rbase = wq * 32;          // warp's 32-px slab

    float dd[2][4][4];
    #pragma unroll
    for (int mt = 0; mt < 2; ++mt)
        #pragma unroll
        for (int nt = 0; nt < 4; ++nt)
            #pragma unroll
            for (int e = 0; e < 4; ++e) dd[mt][nt][e] = 0.0f;

    #pragma unroll
    for (int kt = 0; kt < 8; ++kt) {
        uint2 bf[4];
        #pragma unroll
        for (int nt = 0; nt < 4; ++nt)
            bf[nt] = *reinterpret_cast<const uint2*>(Ksm + (nt * 8 + g) * KSTR + kt * 8 + 2 * cq);

        #pragma unroll
        for (int mt = 0; mt < 2; ++mt) {
            const int r0 = rbase + mt * 16 + g;          // r0&7 == g, (r0>>2)&1 == g2
            const u32* ap = Cs + r0 * 64 + ((kt ^ g) << 3) + ((2 * cq) ^ (4 * g2));
            uint2 v0 = *reinterpret_cast<const uint2*>(ap);            // (a0, a2)
            uint2 v1 = *reinterpret_cast<const uint2*>(ap + 8 * 64);   // (a1, a3)
            #pragma unroll
            for (int nt = 0; nt < 4; ++nt)
                mma_tf32(dd[mt][nt][0], dd[mt][nt][1], dd[mt][nt][2], dd[mt][nt][3],
                         v0.x, v1.x, v0.y, v1.y, bf[nt].x, bf[nt].y);
        }
    }
    __syncthreads();   // Cs free -> reuse as Dsm[o][w], stride DSTR

    // scatter D fragments into smem (banks 8cq+g distinct per instruction)
    #pragma unroll
    for (int mt = 0; mt < 2; ++mt) {
        const int wl0 = rbase + mt * 16 + g;
        #pragma unroll
        for (int nt = 0; nt < 4; ++nt) {
            const int o0 = nt * 8 + 2 * cq;
            Cs[o0 * DSTR + wl0]           = __float_as_uint(dd[mt][nt][0]);
            Cs[(o0 + 1) * DSTR + wl0]     = __float_as_uint(dd[mt][nt][1]);
            Cs[o0 * DSTR + wl0 + 8]       = __float_as_uint(dd[mt][nt][2]);
            Cs[(o0 + 1) * DSTR + wl0 + 8] = __float_as_uint(dd[mt][nt][3]);
        }
    }
    __syncthreads();

    // coalesced stores: warp wq handles o = wq*8 .. wq*8+7, lane covers 4 w's
    const int wb = blockIdx.x * 128 + lane * 4;
    #pragma unroll
    for (int oo = 0; oo < 8; ++oo) {
        const int o = wq * 8 + oo;
        uint4 v = *reinterpret_cast<const uint4*>(Cs + o * DSTR + lane * 4);
        float* p = out + (b * 32 + o) * OUT_PLANE + h * WP + wb;
        // (h*WP + wb) is even -> float2 aligned; wb <= 508 so first pair in-bounds
        *reinterpret_cast<float2*>(p) =
            make_float2(__uint_as_float(v.x), __uint_as_float(v.y));
        if (wb + 2 < WP)
            *reinterpret_cast<float2*>(p + 2) =
                make_float2(__uint_as_float(v.z), __uint_as_float(v.w));
    }
}

extern "C" void kernel_launch(void* const* d_in, const int* in_sizes, int n_in,
                              void* d_out, int out_size)
{
    const float* x = nullptr; const float* kern = nullptr; const float* pts = nullptr;
    for (int i = 0; i < n_in; ++i) {
        if (in_sizes[i] == 8388608)      x    = (const float*)d_in[i];
        else if (in_sizes[i] == 2048)    kern = (const float*)d_in[i];
        else if (in_sizes[i] == 1572864) pts  = (const float*)d_in[i];
    }
    dim3 grid(4, 62, 16);   // 4 w-tiles of 128, 62 h rows, batch
    flex_conv_mma10_kernel<<<grid, 128>>>(x, kern, pts, (float*)d_out);
}